// round 11
// baseline (speedup 1.0000x reference)
#include <cuda_runtime.h>

#define N_FEAT 96
#define MAX_N  50000
#define MAX_E  800000
#define CAP    96      // fixed edge-slot capacity per dst node (deg ~ Poisson(16))

// Scratch (device globals; no allocation allowed)
__device__ float  g_h1[MAX_N * N_FEAT];       // intermediate hop result
__device__ int    g_degi[MAX_N];              // in-degree (final)
__device__ int    g_cnt[MAX_N];               // scatter cursor
__device__ int2   g_slots[MAX_N * CAP];       // (src, norm) fixed slots per dst
__device__ int    g_is64;

// ---------------------------------------------------------------------------
// Fused: zero degi+cnt (all blocks) + dtype detection (block 0 only).
__global__ void k_zero_detect(const unsigned int* __restrict__ ei32, int N, int E) {
    int i = blockIdx.x * blockDim.x + threadIdx.x;
    if (i < N) { g_degi[i] = 0; g_cnt[i] = 0; }
    if (blockIdx.x == 0) {
        __shared__ unsigned int acc;
        if (threadIdx.x == 0) acc = 0u;
        __syncthreads();
        unsigned int v = 0u;
        int W = 2 * E;
        int stride = W / 1024; if (stride < 1) stride = 1;
        for (int k = threadIdx.x; k < 1024; k += blockDim.x) {
            long long w = ((long long)k * stride) | 1;   // odd word
            if (w < W) v |= ei32[w];
        }
        atomicOr(&acc, v);
        __syncthreads();
        if (threadIdx.x == 0) g_is64 = (acc == 0u) ? 1 : 0;
    }
}

// In-degree count over dst, reading the raw edge buffer (either dtype).
__global__ void k_deg(const void* __restrict__ ei, int E) {
    int e = blockIdx.x * blockDim.x + threadIdx.x;
    if (e >= E) return;
    int d;
    if (g_is64) d = (int)((const long long*)ei)[e + E];
    else        d = ((const int*)ei)[e + E];
    atomicAdd(&g_degi[d], 1);
}

// Scatter edges into fixed-capacity slots, packing (src, norm) per slot.
__global__ void k_scatter(const void* __restrict__ ei, int E) {
    int e = blockIdx.x * blockDim.x + threadIdx.x;
    if (e >= E) return;
    int s, d;
    if (g_is64) {
        const long long* p = (const long long*)ei;
        s = (int)p[e]; d = (int)p[e + E];
    } else {
        const int* p = (const int*)ei;
        s = p[e]; d = p[e + E];
    }
    float nrm = rsqrtf((float)(g_degi[s] + 1)) * rsqrtf((float)(g_degi[d] + 1));
    int pos = atomicAdd(&g_cnt[d], 1);
    if (pos < CAP)
        g_slots[(size_t)d * CAP + pos] = make_int2(s, __float_as_int(nrm));
}

// ---------------------------------------------------------------------------
// One warp per dst node, scalar gathers, 4-edge manual unroll for MLP.
// hout[d,:] = dinv^2 * hin[d,:] + sum norm*hin[src,:]

__device__ __forceinline__ void hop_row(const float* __restrict__ hin,
                                        float* __restrict__ hout,
                                        int node, int lane) {
    int deg = g_degi[node];
    float di = rsqrtf((float)(deg + 1));
    float d2 = di * di;
    if (deg > CAP) deg = CAP;
    const int2* slots = g_slots + (size_t)node * CAP;
    const float* own = hin + (size_t)node * N_FEAT;
    float a0 = d2 * own[lane];
    float a1 = d2 * own[lane + 32];
    float a2 = d2 * own[lane + 64];
    int e = 0;
    for (; e + 4 <= deg; e += 4) {
        // 4 independent slot loads
        int2 e0 = slots[e];
        int2 e1 = slots[e + 1];
        int2 e2 = slots[e + 2];
        int2 e3 = slots[e + 3];
        const float* p0 = hin + (size_t)e0.x * N_FEAT;
        const float* p1 = hin + (size_t)e1.x * N_FEAT;
        const float* p2 = hin + (size_t)e2.x * N_FEAT;
        const float* p3 = hin + (size_t)e3.x * N_FEAT;
        // 12 independent gather loads in flight
        float v00 = p0[lane], v01 = p0[lane + 32], v02 = p0[lane + 64];
        float v10 = p1[lane], v11 = p1[lane + 32], v12 = p1[lane + 64];
        float v20 = p2[lane], v21 = p2[lane + 32], v22 = p2[lane + 64];
        float v30 = p3[lane], v31 = p3[lane + 32], v32 = p3[lane + 64];
        float n0 = __int_as_float(e0.y);
        float n1 = __int_as_float(e1.y);
        float n2 = __int_as_float(e2.y);
        float n3 = __int_as_float(e3.y);
        a0 += n0 * v00 + n1 * v10 + n2 * v20 + n3 * v30;
        a1 += n0 * v01 + n1 * v11 + n2 * v21 + n3 * v31;
        a2 += n0 * v02 + n1 * v12 + n2 * v22 + n3 * v32;
    }
    for (; e < deg; e++) {
        int2 en = slots[e];
        const float* pin = hin + (size_t)en.x * N_FEAT;
        float nrm = __int_as_float(en.y);
        a0 += nrm * pin[lane];
        a1 += nrm * pin[lane + 32];
        a2 += nrm * pin[lane + 64];
    }
    float* po = hout + (size_t)node * N_FEAT;
    po[lane]      = a0;
    po[lane + 32] = a1;
    po[lane + 64] = a2;
}

__global__ void k_hop1(const float* __restrict__ x, int N) {
    int w = (blockIdx.x * blockDim.x + threadIdx.x) >> 5;
    if (w >= N) return;
    hop_row(x, g_h1, w, threadIdx.x & 31);
}

__global__ void k_hop2(float* __restrict__ out, int N) {
    int w = (blockIdx.x * blockDim.x + threadIdx.x) >> 5;
    if (w >= N) return;
    hop_row(g_h1, out, w, threadIdx.x & 31);
}

// ---------------------------------------------------------------------------
extern "C" void kernel_launch(void* const* d_in, const int* in_sizes, int n_in,
                              void* d_out, int out_size) {
    const float* x  = (const float*)d_in[0];
    const void*  ei = d_in[1];
    int N = in_sizes[0] / N_FEAT;      // 50000
    int E = in_sizes[1] / 2;           // 800000
    float* out = (float*)d_out;

    const int T = 256;

    k_zero_detect<<<(N + T - 1) / T, T>>>((const unsigned int*)ei, N, E);
    k_deg    <<<(E + T - 1) / T, T>>>(ei, E);
    k_scatter<<<(E + T - 1) / T, T>>>(ei, E);

    int hopBlocks = (N + (T / 32) - 1) / (T / 32);   // one warp per node
    k_hop1<<<hopBlocks, T>>>(x, N);
    k_hop2<<<hopBlocks, T>>>(out, N);
}

// round 12
// speedup vs baseline: 1.0956x; 1.0956x over previous
#include <cuda_runtime.h>

#define N_FEAT 96
#define MAX_N  50000
#define MAX_E  800000
#define CAP    96      // fixed edge-slot capacity per dst node (deg ~ Poisson(16))

// Scratch (device globals; no allocation allowed)
__device__ float  g_h1[MAX_N * N_FEAT];       // intermediate hop result
__device__ int    g_degi[MAX_N];              // in-degree (final)
__device__ int    g_cnt[MAX_N];               // scatter cursor
__device__ int2   g_slots[MAX_N * CAP];       // (src, norm) fixed slots per dst
__device__ int    g_is64;

// ---------------------------------------------------------------------------
// Fused: zero degi+cnt (all blocks) + dtype detection (block 0 only).
__global__ void k_zero_detect(const unsigned int* __restrict__ ei32, int N, int E) {
    int i = blockIdx.x * blockDim.x + threadIdx.x;
    if (i < N) { g_degi[i] = 0; g_cnt[i] = 0; }
    if (blockIdx.x == 0) {
        __shared__ unsigned int acc;
        if (threadIdx.x == 0) acc = 0u;
        __syncthreads();
        unsigned int v = 0u;
        int W = 2 * E;
        int stride = W / 1024; if (stride < 1) stride = 1;
        for (int k = threadIdx.x; k < 1024; k += blockDim.x) {
            long long w = ((long long)k * stride) | 1;   // odd word
            if (w < W) v |= ei32[w];
        }
        atomicOr(&acc, v);
        __syncthreads();
        if (threadIdx.x == 0) g_is64 = (acc == 0u) ? 1 : 0;
    }
}

// In-degree count over dst, reading the raw edge buffer (either dtype).
__global__ void k_deg(const void* __restrict__ ei, int E) {
    int e = blockIdx.x * blockDim.x + threadIdx.x;
    if (e >= E) return;
    int d;
    if (g_is64) d = (int)((const long long*)ei)[e + E];
    else        d = ((const int*)ei)[e + E];
    atomicAdd(&g_degi[d], 1);
}

// Scatter edges into fixed-capacity slots, packing (src, norm) per slot.
__global__ void k_scatter(const void* __restrict__ ei, int E) {
    int e = blockIdx.x * blockDim.x + threadIdx.x;
    if (e >= E) return;
    int s, d;
    if (g_is64) {
        const long long* p = (const long long*)ei;
        s = (int)p[e]; d = (int)p[e + E];
    } else {
        const int* p = (const int*)ei;
        s = p[e]; d = p[e + E];
    }
    float nrm = rsqrtf((float)(g_degi[s] + 1)) * rsqrtf((float)(g_degi[d] + 1));
    int pos = atomicAdd(&g_cnt[d], 1);
    if (pos < CAP)
        g_slots[(size_t)d * CAP + pos] = make_int2(s, __float_as_int(nrm));
}

// ---------------------------------------------------------------------------
// One warp per dst node: hout[d,:] = dinv^2 * hin[d,:] + sum norm*hin[src,:]
// Scalar 3xLDG.32 per edge (proven fastest form) + depth-1 slot prefetch to
// break the slot-load -> gather serial chain. Regs pinned <= 32 via
// __launch_bounds__ so occupancy stays at 64 warps/SM.

__device__ __forceinline__ void hop_row(const float* __restrict__ hin,
                                        float* __restrict__ hout,
                                        int node, int lane) {
    int deg = g_degi[node];
    float di = rsqrtf((float)(deg + 1));
    float d2 = di * di;
    if (deg > CAP) deg = CAP;
    const int2* slots = g_slots + (size_t)node * CAP;
    const float* own = hin + (size_t)node * N_FEAT;
    float a0 = d2 * own[lane];
    float a1 = d2 * own[lane + 32];
    float a2 = d2 * own[lane + 64];
    if (deg > 0) {
        int2 cur = slots[0];
        for (int e = 0; e < deg; e++) {
            int2 nxt = (e + 1 < deg) ? slots[e + 1] : cur;   // prefetch next slot
            const float* pin = hin + (size_t)cur.x * N_FEAT;
            float nrm = __int_as_float(cur.y);
            a0 += nrm * pin[lane];
            a1 += nrm * pin[lane + 32];
            a2 += nrm * pin[lane + 64];
            cur = nxt;
        }
    }
    float* po = hout + (size_t)node * N_FEAT;
    po[lane]      = a0;
    po[lane + 32] = a1;
    po[lane + 64] = a2;
}

__global__ void __launch_bounds__(256, 8) k_hop1(const float* __restrict__ x, int N) {
    int w = (blockIdx.x * blockDim.x + threadIdx.x) >> 5;
    if (w >= N) return;
    hop_row(x, g_h1, w, threadIdx.x & 31);
}

__global__ void __launch_bounds__(256, 8) k_hop2(float* __restrict__ out, int N) {
    int w = (blockIdx.x * blockDim.x + threadIdx.x) >> 5;
    if (w >= N) return;
    hop_row(g_h1, out, w, threadIdx.x & 31);
}

// ---------------------------------------------------------------------------
extern "C" void kernel_launch(void* const* d_in, const int* in_sizes, int n_in,
                              void* d_out, int out_size) {
    const float* x  = (const float*)d_in[0];
    const void*  ei = d_in[1];
    int N = in_sizes[0] / N_FEAT;      // 50000
    int E = in_sizes[1] / 2;           // 800000
    float* out = (float*)d_out;

    const int T = 256;

    k_zero_detect<<<(N + T - 1) / T, T>>>((const unsigned int*)ei, N, E);
    k_deg    <<<(E + T - 1) / T, T>>>(ei, E);
    k_scatter<<<(E + T - 1) / T, T>>>(ei, E);

    int hopBlocks = (N + (T / 32) - 1) / (T / 32);   // one warp per node
    k_hop1<<<hopBlocks, T>>>(x, N);
    k_hop2<<<hopBlocks, T>>>(out, N);
}

// round 13
// speedup vs baseline: 1.1535x; 1.0529x over previous
#include <cuda_runtime.h>

#define N_FEAT 96
#define MAX_N  50000
#define MAX_E  800000
#define CAP    96      // fixed edge-slot capacity per dst node (deg ~ Poisson(16))

// Scratch (device globals; no allocation allowed)
__device__ float  g_h1[MAX_N * N_FEAT];       // intermediate hop result
__device__ int    g_degi[MAX_N];              // in-degree (final)
__device__ int    g_cnt[MAX_N];               // scatter cursor
__device__ int2   g_slots[MAX_N * CAP];       // (src, norm) fixed slots per dst
__device__ int    g_is64;

// ---------------------------------------------------------------------------
// Fused: zero degi+cnt (all blocks) + dtype detection (block 0 only).
__global__ void k_zero_detect(const unsigned int* __restrict__ ei32, int N, int E) {
    int i = blockIdx.x * blockDim.x + threadIdx.x;
    if (i < N) { g_degi[i] = 0; g_cnt[i] = 0; }
    if (blockIdx.x == 0) {
        __shared__ unsigned int acc;
        if (threadIdx.x == 0) acc = 0u;
        __syncthreads();
        unsigned int v = 0u;
        int W = 2 * E;
        int stride = W / 1024; if (stride < 1) stride = 1;
        for (int k = threadIdx.x; k < 1024; k += blockDim.x) {
            long long w = ((long long)k * stride) | 1;   // odd word
            if (w < W) v |= ei32[w];
        }
        atomicOr(&acc, v);
        __syncthreads();
        if (threadIdx.x == 0) g_is64 = (acc == 0u) ? 1 : 0;
    }
}

// In-degree count over dst, reading the raw edge buffer (either dtype).
__global__ void k_deg(const void* __restrict__ ei, int E) {
    int e = blockIdx.x * blockDim.x + threadIdx.x;
    if (e >= E) return;
    int d;
    if (g_is64) d = (int)((const long long*)ei)[e + E];
    else        d = ((const int*)ei)[e + E];
    atomicAdd(&g_degi[d], 1);
}

// Scatter edges into fixed-capacity slots, packing (src, norm) per slot.
__global__ void k_scatter(const void* __restrict__ ei, int E) {
    int e = blockIdx.x * blockDim.x + threadIdx.x;
    if (e >= E) return;
    int s, d;
    if (g_is64) {
        const long long* p = (const long long*)ei;
        s = (int)p[e]; d = (int)p[e + E];
    } else {
        const int* p = (const int*)ei;
        s = p[e]; d = p[e + E];
    }
    float nrm = rsqrtf((float)(g_degi[s] + 1)) * rsqrtf((float)(g_degi[d] + 1));
    int pos = atomicAdd(&g_cnt[d], 1);
    if (pos < CAP)
        g_slots[(size_t)d * CAP + pos] = make_int2(s, __float_as_int(nrm));
}

// ---------------------------------------------------------------------------
// One warp per dst node: hout[d,:] = dinv^2 * hin[d,:] + sum norm*hin[src,:]
// Slots are staged warp-cooperatively into shared memory (coalesced LDG.64),
// the edge loop reads them via broadcast LDS. 2 warps per CTA to minimize
// max-of-warps finish-time inflation from Poisson degree variance.

#define HOP_T 64   // 2 warps per block

template <typename DUMMY = void>
__device__ __forceinline__ void hop_row_staged(const float* __restrict__ hin,
                                               float* __restrict__ hout,
                                               int2* __restrict__ ss,
                                               int node, int lane) {
    int deg = g_degi[node];
    float di = rsqrtf((float)(deg + 1));
    float d2 = di * di;
    if (deg > CAP) deg = CAP;
    const int2* slots = g_slots + (size_t)node * CAP;
    // cooperative staging: coalesced LDG.64, up to 3 iterations
    for (int b = lane; b < deg; b += 32) ss[b] = slots[b];
    __syncwarp();
    const float* own = hin + (size_t)node * N_FEAT;
    float a0 = d2 * own[lane];
    float a1 = d2 * own[lane + 32];
    float a2 = d2 * own[lane + 64];
    for (int e = 0; e < deg; e++) {
        int2 en = ss[e];                    // LDS broadcast (29 cyc)
        const float* pin = hin + (size_t)en.x * N_FEAT;
        float nrm = __int_as_float(en.y);
        a0 += nrm * pin[lane];
        a1 += nrm * pin[lane + 32];
        a2 += nrm * pin[lane + 64];
    }
    float* po = hout + (size_t)node * N_FEAT;
    po[lane]      = a0;
    po[lane + 32] = a1;
    po[lane + 64] = a2;
}

__global__ void __launch_bounds__(HOP_T, 16) k_hop1(const float* __restrict__ x, int N) {
    __shared__ int2 ss[HOP_T / 32][CAP];
    int w = (blockIdx.x * blockDim.x + threadIdx.x) >> 5;
    if (w >= N) return;
    hop_row_staged(x, g_h1, ss[threadIdx.x >> 5], w, threadIdx.x & 31);
}

__global__ void __launch_bounds__(HOP_T, 16) k_hop2(float* __restrict__ out, int N) {
    __shared__ int2 ss[HOP_T / 32][CAP];
    int w = (blockIdx.x * blockDim.x + threadIdx.x) >> 5;
    if (w >= N) return;
    hop_row_staged(g_h1, out, ss[threadIdx.x >> 5], w, threadIdx.x & 31);
}

// ---------------------------------------------------------------------------
extern "C" void kernel_launch(void* const* d_in, const int* in_sizes, int n_in,
                              void* d_out, int out_size) {
    const float* x  = (const float*)d_in[0];
    const void*  ei = d_in[1];
    int N = in_sizes[0] / N_FEAT;      // 50000
    int E = in_sizes[1] / 2;           // 800000
    float* out = (float*)d_out;

    const int T = 256;

    k_zero_detect<<<(N + T - 1) / T, T>>>((const unsigned int*)ei, N, E);
    k_deg    <<<(E + T - 1) / T, T>>>(ei, E);
    k_scatter<<<(E + T - 1) / T, T>>>(ei, E);

    int hopBlocks = (N + (HOP_T / 32) - 1) / (HOP_T / 32);   // one warp per node
    k_hop1<<<hopBlocks, HOP_T>>>(x, N);
    k_hop2<<<hopBlocks, HOP_T>>>(out, N);
}

// round 16
// speedup vs baseline: 1.2109x; 1.0497x over previous
#include <cuda_runtime.h>

#define N_FEAT 96
#define MAX_N  50000
#define MAX_E  800000
#define CAP    96      // fixed edge-slot capacity per dst node (deg ~ Poisson(16))

// Scratch (device globals; no allocation allowed)
__device__ float  g_h1[MAX_N * N_FEAT];       // intermediate hop result
__device__ int    g_degi[MAX_N];              // in-degree (final)
__device__ int    g_cnt[MAX_N];               // scatter cursor
__device__ int2   g_slots[MAX_N * CAP];       // (src, norm) fixed slots per dst
__device__ int    g_is64;

// ---------------------------------------------------------------------------
// Fused: zero degi+cnt (all blocks) + dtype detection (block 0 only).
__global__ void k_zero_detect(const unsigned int* __restrict__ ei32, int N, int E) {
    int i = blockIdx.x * blockDim.x + threadIdx.x;
    if (i < N) { g_degi[i] = 0; g_cnt[i] = 0; }
    if (blockIdx.x == 0) {
        __shared__ unsigned int acc;
        if (threadIdx.x == 0) acc = 0u;
        __syncthreads();
        unsigned int v = 0u;
        int W = 2 * E;
        int stride = W / 1024; if (stride < 1) stride = 1;
        for (int k = threadIdx.x; k < 1024; k += blockDim.x) {
            long long w = ((long long)k * stride) | 1;   // odd word
            if (w < W) v |= ei32[w];
        }
        atomicOr(&acc, v);
        __syncthreads();
        if (threadIdx.x == 0) g_is64 = (acc == 0u) ? 1 : 0;
    }
}

// In-degree count over dst, reading the raw edge buffer (either dtype).
__global__ void k_deg(const void* __restrict__ ei, int E) {
    int e = blockIdx.x * blockDim.x + threadIdx.x;
    if (e >= E) return;
    int d;
    if (g_is64) d = (int)((const long long*)ei)[e + E];
    else        d = ((const int*)ei)[e + E];
    atomicAdd(&g_degi[d], 1);
}

// Scatter edges into fixed-capacity slots, packing (src, norm) per slot.
__global__ void k_scatter(const void* __restrict__ ei, int E) {
    int e = blockIdx.x * blockDim.x + threadIdx.x;
    if (e >= E) return;
    int s, d;
    if (g_is64) {
        const long long* p = (const long long*)ei;
        s = (int)p[e]; d = (int)p[e + E];
    } else {
        const int* p = (const int*)ei;
        s = p[e]; d = p[e + E];
    }
    float nrm = rsqrtf((float)(g_degi[s] + 1)) * rsqrtf((float)(g_degi[d] + 1));
    int pos = atomicAdd(&g_cnt[d], 1);
    if (pos < CAP)
        g_slots[(size_t)d * CAP + pos] = make_int2(s, __float_as_int(nrm));
}

// ---------------------------------------------------------------------------
// One warp per dst node: hout[d,:] = dinv^2 * hin[d,:] + sum norm*hin[src,:]
// Slots staged warp-cooperatively into shared memory (coalesced LDG), edge
// loop reads them via broadcast LDS. 2 warps/CTA for low max-of-warps skew;
// __launch_bounds__(64, 32) pins regs <= 32 so we run at full occupancy.

#define HOP_T 64   // 2 warps per block

__device__ __forceinline__ void hop_row_staged(const float* __restrict__ hin,
                                               float* __restrict__ hout,
                                               int2* __restrict__ ss,
                                               int node, int lane) {
    int deg = g_degi[node];
    float di = rsqrtf((float)(deg + 1));
    float d2 = di * di;
    if (deg > CAP) deg = CAP;
    const int2* slots = g_slots + (size_t)node * CAP;
    // cooperative staging: coalesced loads, up to 3 iterations
    for (int b = lane; b < deg; b += 32) ss[b] = slots[b];
    __syncwarp();
    const float* own = hin + (size_t)node * N_FEAT;
    float a0 = d2 * own[lane];
    float a1 = d2 * own[lane + 32];
    float a2 = d2 * own[lane + 64];
    for (int e = 0; e < deg; e++) {
        int2 en = ss[e];                    // LDS broadcast
        const float* pin = hin + (size_t)en.x * N_FEAT;
        float nrm = __int_as_float(en.y);
        a0 += nrm * pin[lane];
        a1 += nrm * pin[lane + 32];
        a2 += nrm * pin[lane + 64];
    }
    float* po = hout + (size_t)node * N_FEAT;
    po[lane]      = a0;
    po[lane + 32] = a1;
    po[lane + 64] = a2;
}

__global__ void __launch_bounds__(HOP_T, 32) k_hop1(const float* __restrict__ x, int N) {
    __shared__ int2 ss[HOP_T / 32][CAP];
    int w = (blockIdx.x * blockDim.x + threadIdx.x) >> 5;
    if (w >= N) return;
    hop_row_staged(x, g_h1, ss[threadIdx.x >> 5], w, threadIdx.x & 31);
}

__global__ void __launch_bounds__(HOP_T, 32) k_hop2(float* __restrict__ out, int N) {
    __shared__ int2 ss[HOP_T / 32][CAP];
    int w = (blockIdx.x * blockDim.x + threadIdx.x) >> 5;
    if (w >= N) return;
    hop_row_staged(g_h1, out, ss[threadIdx.x >> 5], w, threadIdx.x & 31);
}

// ---------------------------------------------------------------------------
extern "C" void kernel_launch(void* const* d_in, const int* in_sizes, int n_in,
                              void* d_out, int out_size) {
    const float* x  = (const float*)d_in[0];
    const void*  ei = d_in[1];
    int N = in_sizes[0] / N_FEAT;      // 50000
    int E = in_sizes[1] / 2;           // 800000
    float* out = (float*)d_out;

    const int T = 256;

    k_zero_detect<<<(N + T - 1) / T, T>>>((const unsigned int*)ei, N, E);
    k_deg    <<<(E + T - 1) / T, T>>>(ei, E);
    k_scatter<<<(E + T - 1) / T, T>>>(ei, E);

    int hopBlocks = (N + (HOP_T / 32) - 1) / (HOP_T / 32);   // one warp per node
    k_hop1<<<hopBlocks, HOP_T>>>(x, N);
    k_hop2<<<hopBlocks, HOP_T>>>(out, N);
}